// round 1
// baseline (speedup 1.0000x reference)
#include <cuda_runtime.h>
#include <math.h>

#define HIDDEN 4096
#define NH 32
#define NKV 8
#define HD 128
#define BATCH 2
#define SEQ 2048
#define MTOT (BATCH*SEQ)

// Scratch (allocation-free rule: __device__ globals)
__device__ float g_q[(size_t)MTOT * NH * HD];     // 64 MB
__device__ float g_k[(size_t)MTOT * NKV * HD];    // 16 MB
__device__ float g_v[(size_t)MTOT * NKV * HD];    // 16 MB
__device__ float g_attn[(size_t)MTOT * NH * HD];  // 64 MB

// ---------------------------------------------------------------------------
// GEMM: C[M,N] = A[M,K] @ W[N,K]^T   (both A and W are K-contiguous)
// 128x128 tile, BK=16, 256 threads, 8x8 per thread.
// ---------------------------------------------------------------------------
__global__ void __launch_bounds__(256) gemm_nt_kernel(
    const float* __restrict__ A, const float* __restrict__ W,
    float* __restrict__ C, int M, int N, int K)
{
    __shared__ float As[16][128];
    __shared__ float Ws[16][128];

    const int tid = threadIdx.x;
    const int tx = tid & 15, ty = tid >> 4;
    const int m0 = blockIdx.y * 128, n0 = blockIdx.x * 128;
    const int lrow = tid >> 2;            // 0..63
    const int lcol = (tid & 3) << 2;      // 0,4,8,12

    float acc[8][8];
#pragma unroll
    for (int i = 0; i < 8; i++)
#pragma unroll
        for (int j = 0; j < 8; j++) acc[i][j] = 0.f;

    for (int k0 = 0; k0 < K; k0 += 16) {
#pragma unroll
        for (int i = 0; i < 2; i++) {
            const int r = lrow + (i << 6);
            float4 av = *(const float4*)&A[(size_t)(m0 + r) * K + k0 + lcol];
            As[lcol + 0][r] = av.x; As[lcol + 1][r] = av.y;
            As[lcol + 2][r] = av.z; As[lcol + 3][r] = av.w;
            float4 wv = *(const float4*)&W[(size_t)(n0 + r) * K + k0 + lcol];
            Ws[lcol + 0][r] = wv.x; Ws[lcol + 1][r] = wv.y;
            Ws[lcol + 2][r] = wv.z; Ws[lcol + 3][r] = wv.w;
        }
        __syncthreads();

#pragma unroll
        for (int k = 0; k < 16; k++) {
            float4 a0 = *(const float4*)&As[k][ty << 2];
            float4 a1 = *(const float4*)&As[k][(ty << 2) + 64];
            float4 b0 = *(const float4*)&Ws[k][tx << 2];
            float4 b1 = *(const float4*)&Ws[k][(tx << 2) + 64];
            float a[8] = {a0.x, a0.y, a0.z, a0.w, a1.x, a1.y, a1.z, a1.w};
            float b[8] = {b0.x, b0.y, b0.z, b0.w, b1.x, b1.y, b1.z, b1.w};
#pragma unroll
            for (int i = 0; i < 8; i++)
#pragma unroll
                for (int j = 0; j < 8; j++)
                    acc[i][j] += a[i] * b[j];
        }
        __syncthreads();
    }

#pragma unroll
    for (int i = 0; i < 8; i++) {
        const int m = m0 + ((i < 4) ? ((ty << 2) + i) : (64 + (ty << 2) + i - 4));
        float4 c0 = make_float4(acc[i][0], acc[i][1], acc[i][2], acc[i][3]);
        float4 c1 = make_float4(acc[i][4], acc[i][5], acc[i][6], acc[i][7]);
        *(float4*)&C[(size_t)m * N + n0 + (tx << 2)] = c0;
        *(float4*)&C[(size_t)m * N + n0 + 64 + (tx << 2)] = c1;
    }
}

// ---------------------------------------------------------------------------
// Fused per-head LayerNorm + RoPE, in place.
// One block of 128 threads per (b, s, head).
// ---------------------------------------------------------------------------
__global__ void __launch_bounds__(128) norm_rope_kernel(
    float* __restrict__ x, const float* __restrict__ w,
    const int* __restrict__ pos_ids, int H)
{
    const int idx = blockIdx.x;          // b*SEQ*H + s*H + h
    const int h = idx % H;
    const int s = (idx / H) % SEQ;
    float* xp = x + (size_t)idx * HD;

    const int t = threadIdx.x;
    const int lane = t & 31, wid = t >> 5;

    __shared__ float red[4];
    __shared__ float sx[128];

    float v = xp[t];

    float sum = v;
#pragma unroll
    for (int o = 16; o; o >>= 1) sum += __shfl_xor_sync(~0u, sum, o);
    if (!lane) red[wid] = sum;
    __syncthreads();
    const float mean = (red[0] + red[1] + red[2] + red[3]) * (1.f / 128.f);

    const float d = v - mean;
    float s2 = d * d;
#pragma unroll
    for (int o = 16; o; o >>= 1) s2 += __shfl_xor_sync(~0u, s2, o);
    __syncthreads();
    if (!lane) red[wid] = s2;
    __syncthreads();
    const float var = (red[0] + red[1] + red[2] + red[3]) * (1.f / 128.f);

    const float xn = d * rsqrtf(var + 1e-5f) * w[h * HD + t];
    sx[t] = xn;
    __syncthreads();

    // RoPE: inv_freq_i = 10000^(-2i/128) = exp(-i * ln(10000)/64)
    const int i = t & 63;
    const float ang = (float)pos_ids[s] * __expf(-(float)i * 0.14391156831212787f);
    float sn, cs;
    sincosf(ang, &sn, &cs);
    float out;
    if (t < 64) out = xn * cs - sx[t + 64] * sn;
    else        out = xn * cs + sx[t - 64] * sn;
    xp[t] = out;
}

// ---------------------------------------------------------------------------
// Causal flash attention, fp32, online softmax.
// Q: [B,S,NH,HD]  K,V: [B,S,NKV,HD]  O: [B,S,NH*HD]
// Block = (q_tile, head, batch); 256 threads as 16x16; 64x64 tiles.
// ---------------------------------------------------------------------------
#define SQ_STR 129
#define SV_STR 128
#define SP_STR 65

__global__ void __launch_bounds__(256) flash_attn_kernel(
    const float* __restrict__ Q, const float* __restrict__ K,
    const float* __restrict__ V, float* __restrict__ O)
{
    extern __shared__ float sm[];
    float* sQ = sm;                       // 64 * 129
    float* sK = sQ + 64 * SQ_STR;         // 64 * 129
    float* sV = sK + 64 * SQ_STR;         // 64 * 128
    float* sP = sV + 64 * SV_STR;         // 64 * 65

    const int qt = blockIdx.x, h = blockIdx.y, b = blockIdx.z;
    const int kvh = h >> 2;
    const int tid = threadIdx.x;
    const int tx = tid & 15, ty = tid >> 4;
    const float scale = 0.08838834764831845f;   // 1/sqrt(128)

    // Load Q tile (64 x 128)
    for (int i = tid; i < 64 * 32; i += 256) {
        const int r = i >> 5, c4 = (i & 31) << 2;
        float4 qv = *(const float4*)&Q[(((size_t)(b * SEQ + qt * 64 + r)) * NH + h) * HD + c4];
        sQ[r * SQ_STR + c4 + 0] = qv.x; sQ[r * SQ_STR + c4 + 1] = qv.y;
        sQ[r * SQ_STR + c4 + 2] = qv.z; sQ[r * SQ_STR + c4 + 3] = qv.w;
    }

    float m_i[4], l_i[4], o[4][8];
#pragma unroll
    for (int i = 0; i < 4; i++) {
        m_i[i] = -1e30f; l_i[i] = 0.f;
#pragma unroll
        for (int c = 0; c < 8; c++) o[i][c] = 0.f;
    }

    for (int j = 0; j <= qt; j++) {
        __syncthreads();   // previous PV done; safe to overwrite K/V/P

        // Load K, V tiles
        for (int i = tid; i < 64 * 32; i += 256) {
            const int r = i >> 5, c4 = (i & 31) << 2;
            const size_t base = (((size_t)(b * SEQ + j * 64 + r)) * NKV + kvh) * HD + c4;
            float4 kv = *(const float4*)&K[base];
            sK[r * SQ_STR + c4 + 0] = kv.x; sK[r * SQ_STR + c4 + 1] = kv.y;
            sK[r * SQ_STR + c4 + 2] = kv.z; sK[r * SQ_STR + c4 + 3] = kv.w;
            float4 vv = *(const float4*)&V[base];
            *(float4*)&sV[r * SV_STR + c4] = vv;
        }
        __syncthreads();

        // S = Q K^T (each thread: rows ty*4..+3, cols tx*4..+3)
        float sacc[4][4];
#pragma unroll
        for (int i = 0; i < 4; i++)
#pragma unroll
            for (int jj = 0; jj < 4; jj++) sacc[i][jj] = 0.f;

        for (int k = 0; k < HD; k++) {
            float a[4], bb[4];
#pragma unroll
            for (int i = 0; i < 4; i++) a[i] = sQ[(ty * 4 + i) * SQ_STR + k];
#pragma unroll
            for (int jj = 0; jj < 4; jj++) bb[jj] = sK[(tx * 4 + jj) * SQ_STR + k];
#pragma unroll
            for (int i = 0; i < 4; i++)
#pragma unroll
                for (int jj = 0; jj < 4; jj++)
                    sacc[i][jj] += a[i] * bb[jj];
        }

        const bool diag = (j == qt);
#pragma unroll
        for (int i = 0; i < 4; i++) {
            const int grow = qt * 64 + ty * 4 + i;
            float srow[4];
#pragma unroll
            for (int jj = 0; jj < 4; jj++) {
                float sv = sacc[i][jj] * scale;
                if (diag && (j * 64 + tx * 4 + jj) > grow) sv = -1e30f;
                srow[jj] = sv;
            }
            // row max across 16 tx lanes
            float mx = fmaxf(fmaxf(srow[0], srow[1]), fmaxf(srow[2], srow[3]));
#pragma unroll
            for (int ofs = 8; ofs; ofs >>= 1) mx = fmaxf(mx, __shfl_xor_sync(~0u, mx, ofs));
            const float m_new = fmaxf(m_i[i], mx);

            float p[4], rs = 0.f;
#pragma unroll
            for (int jj = 0; jj < 4; jj++) { p[jj] = __expf(srow[jj] - m_new); rs += p[jj]; }
#pragma unroll
            for (int ofs = 8; ofs; ofs >>= 1) rs += __shfl_xor_sync(~0u, rs, ofs);

            const float alpha = __expf(m_i[i] - m_new);
            l_i[i] = l_i[i] * alpha + rs;
            m_i[i] = m_new;
#pragma unroll
            for (int c = 0; c < 8; c++) o[i][c] *= alpha;
#pragma unroll
            for (int jj = 0; jj < 4; jj++)
                sP[(ty * 4 + i) * SP_STR + tx * 4 + jj] = p[jj];
        }
        __syncthreads();

        // O += P @ V  (each thread: rows ty*4..+3, cols tx*8..+7 of 128)
        for (int k = 0; k < 64; k++) {
            float pk[4];
#pragma unroll
            for (int i = 0; i < 4; i++) pk[i] = sP[(ty * 4 + i) * SP_STR + k];
            float4 v0 = *(const float4*)&sV[k * SV_STR + tx * 8];
            float4 v1 = *(const float4*)&sV[k * SV_STR + tx * 8 + 4];
            float vv[8] = {v0.x, v0.y, v0.z, v0.w, v1.x, v1.y, v1.z, v1.w};
#pragma unroll
            for (int i = 0; i < 4; i++)
#pragma unroll
                for (int c = 0; c < 8; c++)
                    o[i][c] += pk[i] * vv[c];
        }
    }

    // Final normalize + write: O layout [b, s, h*128 + d]
#pragma unroll
    for (int i = 0; i < 4; i++) {
        const float inv = 1.f / l_i[i];
        const int row = qt * 64 + ty * 4 + i;
        float4 c0 = make_float4(o[i][0] * inv, o[i][1] * inv, o[i][2] * inv, o[i][3] * inv);
        float4 c1 = make_float4(o[i][4] * inv, o[i][5] * inv, o[i][6] * inv, o[i][7] * inv);
        float* dst = &O[(((size_t)(b * SEQ + row)) * NH + h) * HD + tx * 8];
        *(float4*)&dst[0] = c0;
        *(float4*)&dst[4] = c1;
    }
}

// ---------------------------------------------------------------------------
extern "C" void kernel_launch(void* const* d_in, const int* in_sizes, int n_in,
                              void* d_out, int out_size)
{
    const float* hs = (const float*)d_in[0];
    const int*   pos = (const int*)d_in[1];
    const float* wq = (const float*)d_in[2];
    const float* wk = (const float*)d_in[3];
    const float* wv = (const float*)d_in[4];
    const float* wo = (const float*)d_in[5];
    const float* qn = (const float*)d_in[6];
    const float* kn = (const float*)d_in[7];
    float* out = (float*)d_out;

    float *q, *k, *v, *attn;
    cudaGetSymbolAddress((void**)&q, g_q);
    cudaGetSymbolAddress((void**)&k, g_k);
    cudaGetSymbolAddress((void**)&v, g_v);
    cudaGetSymbolAddress((void**)&attn, g_attn);

    const size_t fa_smem = (size_t)(64 * SQ_STR * 2 + 64 * SV_STR + 64 * SP_STR) * sizeof(float);
    cudaFuncSetAttribute(flash_attn_kernel,
                         cudaFuncAttributeMaxDynamicSharedMemorySize, (int)fa_smem);

    // QKV projections
    gemm_nt_kernel<<<dim3(NH * HD / 128, MTOT / 128), 256>>>(hs, wq, q, MTOT, NH * HD, HIDDEN);
    gemm_nt_kernel<<<dim3(NKV * HD / 128, MTOT / 128), 256>>>(hs, wk, k, MTOT, NKV * HD, HIDDEN);
    gemm_nt_kernel<<<dim3(NKV * HD / 128, MTOT / 128), 256>>>(hs, wv, v, MTOT, NKV * HD, HIDDEN);

    // Per-head LN + RoPE (in place)
    norm_rope_kernel<<<MTOT * NH, 128>>>(q, qn, pos, NH);
    norm_rope_kernel<<<MTOT * NKV, 128>>>(k, kn, pos, NKV);

    // Causal flash attention
    flash_attn_kernel<<<dim3(SEQ / 64, NH, BATCH), 256, fa_smem>>>(q, k, v, attn);

    // Output projection
    gemm_nt_kernel<<<dim3(HIDDEN / 128, MTOT / 128), 256>>>(attn, wo, out, MTOT, HIDDEN, HIDDEN);
}

// round 4
// speedup vs baseline: 1.6863x; 1.6863x over previous
#include <cuda_runtime.h>
#include <math.h>
#include <stdint.h>

#define HIDDEN 4096
#define NH 32
#define NKV 8
#define HD 128
#define BATCH 2
#define SEQ 2048
#define MTOT (BATCH*SEQ)

// Scratch (allocation-free rule: __device__ globals)
__device__ float g_q[(size_t)MTOT * NH * HD];     // 64 MB
__device__ float g_k[(size_t)MTOT * NKV * HD];    // 16 MB
__device__ float g_v[(size_t)MTOT * NKV * HD];    // 16 MB
__device__ float g_attn[(size_t)MTOT * NH * HD];  // 64 MB

// ---------------------------------------------------------------------------
// tf32 helpers
// ---------------------------------------------------------------------------
__device__ __forceinline__ float to_tf32(float x) {
    uint32_t u;
    asm("cvt.rna.tf32.f32 %0, %1;" : "=r"(u) : "f"(x));
    return __uint_as_float(u);
}

__device__ __forceinline__ void mma_tf32(float* c, const uint32_t* a, const uint32_t* b) {
    asm volatile(
        "mma.sync.aligned.m16n8k8.row.col.f32.tf32.tf32.f32 "
        "{%0,%1,%2,%3}, {%4,%5,%6,%7}, {%8,%9}, {%0,%1,%2,%3};"
        : "+f"(c[0]), "+f"(c[1]), "+f"(c[2]), "+f"(c[3])
        : "r"(a[0]), "r"(a[1]), "r"(a[2]), "r"(a[3]), "r"(b[0]), "r"(b[1]));
}

// ---------------------------------------------------------------------------
// tf32 tensor-core GEMM: C[M,N] = A[M,K] @ W[N,K]^T
// CTA tile 128x128, BK=32, 256 threads (8 warps), warp tile 64x32.
// PTX m16n8k8.tf32 fragment layout (gid=lane>>2, tig=lane&3):
//   a0=A[gid][tig]  a1=A[gid+8][tig]  a2=A[gid][tig+4]  a3=A[gid+8][tig+4]
//   b0=B[tig][gid]  b1=B[tig+4][gid]
//   c0=(gid,2tig) c1=(gid,2tig+1) c2=(gid+8,2tig) c3=(gid+8,2tig+1)
// ---------------------------------------------------------------------------
#define GBM 128
#define GBN 128
#define GBK 32
#define GSTR 40
#define GBUF (128*GSTR)

__global__ void __launch_bounds__(256) gemm_tf32_kernel(
    const float* __restrict__ A, const float* __restrict__ W,
    float* __restrict__ C, int M, int N, int K)
{
    extern __shared__ float sm[];
    float* sA = sm;               // 2 buffers of 128*40
    float* sB = sm + 2 * GBUF;    // 2 buffers of 128*40

    const int tid  = threadIdx.x;
    const int lane = tid & 31;
    const int wid  = tid >> 5;
    const int wm   = wid & 1;     // 0..1 -> 64-row slab
    const int wn   = wid >> 1;    // 0..3 -> 32-col slab
    const int gid  = lane >> 2;   // 0..7
    const int tig  = lane & 3;    // 0..3

    const int m0 = blockIdx.y * GBM;
    const int n0 = blockIdx.x * GBN;

    // gmem load mapping: 1024 float4 per operand tile, 4 per thread
    const int lr0 = tid >> 3;            // row 0..31 (+32 per step)
    const int lc4 = (tid & 7) << 2;      // k offset 0..28

    float acc[4][4][4];
#pragma unroll
    for (int i = 0; i < 4; i++)
#pragma unroll
        for (int j = 0; j < 4; j++)
#pragma unroll
            for (int c = 0; c < 4; c++) acc[i][j][c] = 0.f;

    float4 pa[4], pb[4];

    // prefetch tile 0
#pragma unroll
    for (int i = 0; i < 4; i++) {
        const int r = lr0 + i * 32;
        pa[i] = *(const float4*)&A[(size_t)(m0 + r) * K + lc4];
        pb[i] = *(const float4*)&W[(size_t)(n0 + r) * K + lc4];
    }
    // store tile 0 to buffer 0 (with RN tf32 rounding)
#pragma unroll
    for (int i = 0; i < 4; i++) {
        const int r = lr0 + i * 32;
        float* da = &sA[r * GSTR + lc4];
        da[0] = to_tf32(pa[i].x); da[1] = to_tf32(pa[i].y);
        da[2] = to_tf32(pa[i].z); da[3] = to_tf32(pa[i].w);
        float* db = &sB[r * GSTR + lc4];
        db[0] = to_tf32(pb[i].x); db[1] = to_tf32(pb[i].y);
        db[2] = to_tf32(pb[i].z); db[3] = to_tf32(pb[i].w);
    }
    __syncthreads();

    const int ntiles = K / GBK;
    for (int t = 0; t < ntiles; t++) {
        const int cur = (t & 1) * GBUF;

        // prefetch next tile into registers (overlaps MMA work)
        if (t + 1 < ntiles) {
            const size_t k0 = (size_t)(t + 1) * GBK;
#pragma unroll
            for (int i = 0; i < 4; i++) {
                const int r = lr0 + i * 32;
                pa[i] = *(const float4*)&A[(size_t)(m0 + r) * K + k0 + lc4];
                pb[i] = *(const float4*)&W[(size_t)(n0 + r) * K + k0 + lc4];
            }
        }

        // compute: 4 k-steps of 8
#pragma unroll
        for (int kk = 0; kk < GBK; kk += 8) {
            uint32_t afr[4][4], bfr[4][2];
#pragma unroll
            for (int im = 0; im < 4; im++) {
                const int r = wm * 64 + im * 16 + gid;
                afr[im][0] = __float_as_uint(sA[cur + r * GSTR + kk + tig]);
                afr[im][1] = __float_as_uint(sA[cur + (r + 8) * GSTR + kk + tig]);
                afr[im][2] = __float_as_uint(sA[cur + r * GSTR + kk + tig + 4]);
                afr[im][3] = __float_as_uint(sA[cur + (r + 8) * GSTR + kk + tig + 4]);
            }
#pragma unroll
            for (int jn = 0; jn < 4; jn++) {
                const int n = wn * 32 + jn * 8 + gid;
                bfr[jn][0] = __float_as_uint(sB[cur + n * GSTR + kk + tig]);
                bfr[jn][1] = __float_as_uint(sB[cur + n * GSTR + kk + tig + 4]);
            }
#pragma unroll
            for (int im = 0; im < 4; im++)
#pragma unroll
                for (int jn = 0; jn < 4; jn++)
                    mma_tf32(acc[im][jn], afr[im], bfr[jn]);
        }

        // store prefetched tile to the other buffer
        if (t + 1 < ntiles) {
            const int nxt = ((t + 1) & 1) * GBUF;
#pragma unroll
            for (int i = 0; i < 4; i++) {
                const int r = lr0 + i * 32;
                float* da = &sA[nxt + r * GSTR + lc4];
                da[0] = to_tf32(pa[i].x); da[1] = to_tf32(pa[i].y);
                da[2] = to_tf32(pa[i].z); da[3] = to_tf32(pa[i].w);
                float* db = &sB[nxt + r * GSTR + lc4];
                db[0] = to_tf32(pb[i].x); db[1] = to_tf32(pb[i].y);
                db[2] = to_tf32(pb[i].z); db[3] = to_tf32(pb[i].w);
            }
        }
        __syncthreads();
    }

    // epilogue
#pragma unroll
    for (int im = 0; im < 4; im++) {
#pragma unroll
        for (int jn = 0; jn < 4; jn++) {
            const int row = m0 + wm * 64 + im * 16 + gid;
            const int col = n0 + wn * 32 + jn * 8 + 2 * tig;
            *(float2*)&C[(size_t)row * N + col]       = make_float2(acc[im][jn][0], acc[im][jn][1]);
            *(float2*)&C[(size_t)(row + 8) * N + col] = make_float2(acc[im][jn][2], acc[im][jn][3]);
        }
    }
}

// ---------------------------------------------------------------------------
// Fused per-head LayerNorm + RoPE, in place.
// ---------------------------------------------------------------------------
__global__ void __launch_bounds__(128) norm_rope_kernel(
    float* __restrict__ x, const float* __restrict__ w,
    const int* __restrict__ pos_ids, int H)
{
    const int idx = blockIdx.x;          // b*SEQ*H + s*H + h
    const int h = idx % H;
    const int s = (idx / H) % SEQ;
    float* xp = x + (size_t)idx * HD;

    const int t = threadIdx.x;
    const int lane = t & 31, wid = t >> 5;

    __shared__ float red[4];
    __shared__ float sx[128];

    float v = xp[t];

    float sum = v;
#pragma unroll
    for (int o = 16; o; o >>= 1) sum += __shfl_xor_sync(~0u, sum, o);
    if (!lane) red[wid] = sum;
    __syncthreads();
    const float mean = (red[0] + red[1] + red[2] + red[3]) * (1.f / 128.f);

    const float d = v - mean;
    float s2 = d * d;
#pragma unroll
    for (int o = 16; o; o >>= 1) s2 += __shfl_xor_sync(~0u, s2, o);
    __syncthreads();
    if (!lane) red[wid] = s2;
    __syncthreads();
    const float var = (red[0] + red[1] + red[2] + red[3]) * (1.f / 128.f);

    const float xn = d * rsqrtf(var + 1e-5f) * w[h * HD + t];
    sx[t] = xn;
    __syncthreads();

    const int i = t & 63;
    const float ang = (float)pos_ids[s] * __expf(-(float)i * 0.14391156831212787f);
    float sn, cs;
    sincosf(ang, &sn, &cs);
    float out;
    if (t < 64) out = xn * cs - sx[t + 64] * sn;
    else        out = xn * cs + sx[t - 64] * sn;
    xp[t] = out;
}

// ---------------------------------------------------------------------------
// Causal flash attention, fp32, online softmax. (unchanged from R1)
// ---------------------------------------------------------------------------
#define SQ_STR 129
#define SV_STR 128
#define SP_STR 65

__global__ void __launch_bounds__(256) flash_attn_kernel(
    const float* __restrict__ Q, const float* __restrict__ K,
    const float* __restrict__ V, float* __restrict__ O)
{
    extern __shared__ float sm[];
    float* sQ = sm;                       // 64 * 129
    float* sK = sQ + 64 * SQ_STR;         // 64 * 129
    float* sV = sK + 64 * SQ_STR;         // 64 * 128
    float* sP = sV + 64 * SV_STR;         // 64 * 65

    const int qt = blockIdx.x, h = blockIdx.y, b = blockIdx.z;
    const int kvh = h >> 2;
    const int tid = threadIdx.x;
    const int tx = tid & 15, ty = tid >> 4;
    const float scale = 0.08838834764831845f;   // 1/sqrt(128)

    for (int i = tid; i < 64 * 32; i += 256) {
        const int r = i >> 5, c4 = (i & 31) << 2;
        float4 qv = *(const float4*)&Q[(((size_t)(b * SEQ + qt * 64 + r)) * NH + h) * HD + c4];
        sQ[r * SQ_STR + c4 + 0] = qv.x; sQ[r * SQ_STR + c4 + 1] = qv.y;
        sQ[r * SQ_STR + c4 + 2] = qv.z; sQ[r * SQ_STR + c4 + 3] = qv.w;
    }

    float m_i[4], l_i[4], o[4][8];
#pragma unroll
    for (int i = 0; i < 4; i++) {
        m_i[i] = -1e30f; l_i[i] = 0.f;
#pragma unroll
        for (int c = 0; c < 8; c++) o[i][c] = 0.f;
    }

    for (int j = 0; j <= qt; j++) {
        __syncthreads();

        for (int i = tid; i < 64 * 32; i += 256) {
            const int r = i >> 5, c4 = (i & 31) << 2;
            const size_t base = (((size_t)(b * SEQ + j * 64 + r)) * NKV + kvh) * HD + c4;
            float4 kv = *(const float4*)&K[base];
            sK[r * SQ_STR + c4 + 0] = kv.x; sK[r * SQ_STR + c4 + 1] = kv.y;
            sK[r * SQ_STR + c4 + 2] = kv.z; sK[r * SQ_STR + c4 + 3] = kv.w;
            float4 vv = *(const float4*)&V[base];
            *(float4*)&sV[r * SV_STR + c4] = vv;
        }
        __syncthreads();

        float sacc[4][4];
#pragma unroll
        for (int i = 0; i < 4; i++)
#pragma unroll
            for (int jj = 0; jj < 4; jj++) sacc[i][jj] = 0.f;

        for (int k = 0; k < HD; k++) {
            float a[4], bb[4];
#pragma unroll
            for (int i = 0; i < 4; i++) a[i] = sQ[(ty * 4 + i) * SQ_STR + k];
#pragma unroll
            for (int jj = 0; jj < 4; jj++) bb[jj] = sK[(tx * 4 + jj) * SQ_STR + k];
#pragma unroll
            for (int i = 0; i < 4; i++)
#pragma unroll
                for (int jj = 0; jj < 4; jj++)
                    sacc[i][jj] += a[i] * bb[jj];
        }

        const bool diag = (j == qt);
#pragma unroll
        for (int i = 0; i < 4; i++) {
            const int grow = qt * 64 + ty * 4 + i;
            float srow[4];
#pragma unroll
            for (int jj = 0; jj < 4; jj++) {
                float sv = sacc[i][jj] * scale;
                if (diag && (j * 64 + tx * 4 + jj) > grow) sv = -1e30f;
                srow[jj] = sv;
            }
            float mx = fmaxf(fmaxf(srow[0], srow[1]), fmaxf(srow[2], srow[3]));
#pragma unroll
            for (int ofs = 8; ofs; ofs >>= 1) mx = fmaxf(mx, __shfl_xor_sync(~0u, mx, ofs));
            const float m_new = fmaxf(m_i[i], mx);

            float p[4], rs = 0.f;
#pragma unroll
            for (int jj = 0; jj < 4; jj++) { p[jj] = __expf(srow[jj] - m_new); rs += p[jj]; }
#pragma unroll
            for (int ofs = 8; ofs; ofs >>= 1) rs += __shfl_xor_sync(~0u, rs, ofs);

            const float alpha = __expf(m_i[i] - m_new);
            l_i[i] = l_i[i] * alpha + rs;
            m_i[i] = m_new;
#pragma unroll
            for (int c = 0; c < 8; c++) o[i][c] *= alpha;
#pragma unroll
            for (int jj = 0; jj < 4; jj++)
                sP[(ty * 4 + i) * SP_STR + tx * 4 + jj] = p[jj];
        }
        __syncthreads();

        for (int k = 0; k < 64; k++) {
            float pk[4];
#pragma unroll
            for (int i = 0; i < 4; i++) pk[i] = sP[(ty * 4 + i) * SP_STR + k];
            float4 v0 = *(const float4*)&sV[k * SV_STR + tx * 8];
            float4 v1 = *(const float4*)&sV[k * SV_STR + tx * 8 + 4];
            float vv[8] = {v0.x, v0.y, v0.z, v0.w, v1.x, v1.y, v1.z, v1.w};
#pragma unroll
            for (int i = 0; i < 4; i++)
#pragma unroll
                for (int c = 0; c < 8; c++)
                    o[i][c] += pk[i] * vv[c];
        }
    }

#pragma unroll
    for (int i = 0; i < 4; i++) {
        const float inv = 1.f / l_i[i];
        const int row = qt * 64 + ty * 4 + i;
        float4 c0 = make_float4(o[i][0] * inv, o[i][1] * inv, o[i][2] * inv, o[i][3] * inv);
        float4 c1 = make_float4(o[i][4] * inv, o[i][5] * inv, o[i][6] * inv, o[i][7] * inv);
        float* dst = &O[(((size_t)(b * SEQ + row)) * NH + h) * HD + tx * 8];
        *(float4*)&dst[0] = c0;
        *(float4*)&dst[4] = c1;
    }
}

// ---------------------------------------------------------------------------
extern "C" void kernel_launch(void* const* d_in, const int* in_sizes, int n_in,
                              void* d_out, int out_size)
{
    const float* hs = (const float*)d_in[0];
    const int*   pos = (const int*)d_in[1];
    const float* wq = (const float*)d_in[2];
    const float* wk = (const float*)d_in[3];
    const float* wv = (const float*)d_in[4];
    const float* wo = (const float*)d_in[5];
    const float* qn = (const float*)d_in[6];
    const float* kn = (const float*)d_in[7];
    float* out = (float*)d_out;

    float *q, *k, *v, *attn;
    cudaGetSymbolAddress((void**)&q, g_q);
    cudaGetSymbolAddress((void**)&k, g_k);
    cudaGetSymbolAddress((void**)&v, g_v);
    cudaGetSymbolAddress((void**)&attn, g_attn);

    const size_t gemm_smem = (size_t)4 * GBUF * sizeof(float);  // 81920 B
    cudaFuncSetAttribute(gemm_tf32_kernel,
                         cudaFuncAttributeMaxDynamicSharedMemorySize, (int)gemm_smem);

    const size_t fa_smem = (size_t)(64 * SQ_STR * 2 + 64 * SV_STR + 64 * SP_STR) * sizeof(float);
    cudaFuncSetAttribute(flash_attn_kernel,
                         cudaFuncAttributeMaxDynamicSharedMemorySize, (int)fa_smem);

    // QKV projections (tensor cores, tf32)
    gemm_tf32_kernel<<<dim3(NH * HD / 128, MTOT / 128), 256, gemm_smem>>>(hs, wq, q, MTOT, NH * HD, HIDDEN);
    gemm_tf32_kernel<<<dim3(NKV * HD / 128, MTOT / 128), 256, gemm_smem>>>(hs, wk, k, MTOT, NKV * HD, HIDDEN);
    gemm_tf32_kernel<<<dim3(NKV * HD / 128, MTOT / 128), 256, gemm_smem>>>(hs, wv, v, MTOT, NKV * HD, HIDDEN);

    // Per-head LN + RoPE (in place)
    norm_rope_kernel<<<MTOT * NH, 128>>>(q, qn, pos, NH);
    norm_rope_kernel<<<MTOT * NKV, 128>>>(k, kn, pos, NKV);

    // Causal flash attention
    flash_attn_kernel<<<dim3(SEQ / 64, NH, BATCH), 256, fa_smem>>>(q, k, v, attn);

    // Output projection (tensor cores, tf32)
    gemm_tf32_kernel<<<dim3(HIDDEN / 128, MTOT / 128), 256, gemm_smem>>>(attn, wo, out, MTOT, HIDDEN, HIDDEN);
}

// round 6
// speedup vs baseline: 2.4415x; 1.4478x over previous
#include <cuda_runtime.h>
#include <math.h>
#include <stdint.h>

#define HIDDEN 4096
#define NH 32
#define NKV 8
#define HD 128
#define BATCH 2
#define SEQ 2048
#define MTOT (BATCH*SEQ)

// Scratch (allocation-free rule: __device__ globals)
__device__ float g_q[(size_t)MTOT * NH * HD];     // 64 MB
__device__ float g_k[(size_t)MTOT * NKV * HD];    // 16 MB
__device__ float g_v[(size_t)MTOT * NKV * HD];    // 16 MB
__device__ float g_attn[(size_t)MTOT * NH * HD];  // 64 MB

// ---------------------------------------------------------------------------
// tf32 helpers
// ---------------------------------------------------------------------------
__device__ __forceinline__ float to_tf32(float x) {
    uint32_t u;
    asm("cvt.rna.tf32.f32 %0, %1;" : "=r"(u) : "f"(x));
    return __uint_as_float(u);
}

__device__ __forceinline__ void mma_tf32(float* c, const uint32_t* a, const uint32_t* b) {
    asm volatile(
        "mma.sync.aligned.m16n8k8.row.col.f32.tf32.tf32.f32 "
        "{%0,%1,%2,%3}, {%4,%5,%6,%7}, {%8,%9}, {%0,%1,%2,%3};"
        : "+f"(c[0]), "+f"(c[1]), "+f"(c[2]), "+f"(c[3])
        : "r"(a[0]), "r"(a[1]), "r"(a[2]), "r"(a[3]), "r"(b[0]), "r"(b[1]));
}

// ---------------------------------------------------------------------------
// tf32 tensor-core GEMM: C[M,N] = A[M,K] @ W[N,K]^T  (unchanged from R3)
// ---------------------------------------------------------------------------
#define GBM 128
#define GBN 128
#define GBK 32
#define GSTR 40
#define GBUF (128*GSTR)

__global__ void __launch_bounds__(256) gemm_tf32_kernel(
    const float* __restrict__ A, const float* __restrict__ W,
    float* __restrict__ C, int M, int N, int K)
{
    extern __shared__ float sm[];
    float* sA = sm;
    float* sB = sm + 2 * GBUF;

    const int tid  = threadIdx.x;
    const int lane = tid & 31;
    const int wid  = tid >> 5;
    const int wm   = wid & 1;
    const int wn   = wid >> 1;
    const int gid  = lane >> 2;
    const int tig  = lane & 3;

    const int m0 = blockIdx.y * GBM;
    const int n0 = blockIdx.x * GBN;

    const int lr0 = tid >> 3;
    const int lc4 = (tid & 7) << 2;

    float acc[4][4][4];
#pragma unroll
    for (int i = 0; i < 4; i++)
#pragma unroll
        for (int j = 0; j < 4; j++)
#pragma unroll
            for (int c = 0; c < 4; c++) acc[i][j][c] = 0.f;

    float4 pa[4], pb[4];

#pragma unroll
    for (int i = 0; i < 4; i++) {
        const int r = lr0 + i * 32;
        pa[i] = *(const float4*)&A[(size_t)(m0 + r) * K + lc4];
        pb[i] = *(const float4*)&W[(size_t)(n0 + r) * K + lc4];
    }
#pragma unroll
    for (int i = 0; i < 4; i++) {
        const int r = lr0 + i * 32;
        float* da = &sA[r * GSTR + lc4];
        da[0] = to_tf32(pa[i].x); da[1] = to_tf32(pa[i].y);
        da[2] = to_tf32(pa[i].z); da[3] = to_tf32(pa[i].w);
        float* db = &sB[r * GSTR + lc4];
        db[0] = to_tf32(pb[i].x); db[1] = to_tf32(pb[i].y);
        db[2] = to_tf32(pb[i].z); db[3] = to_tf32(pb[i].w);
    }
    __syncthreads();

    const int ntiles = K / GBK;
    for (int t = 0; t < ntiles; t++) {
        const int cur = (t & 1) * GBUF;

        if (t + 1 < ntiles) {
            const size_t k0 = (size_t)(t + 1) * GBK;
#pragma unroll
            for (int i = 0; i < 4; i++) {
                const int r = lr0 + i * 32;
                pa[i] = *(const float4*)&A[(size_t)(m0 + r) * K + k0 + lc4];
                pb[i] = *(const float4*)&W[(size_t)(n0 + r) * K + k0 + lc4];
            }
        }

#pragma unroll
        for (int kk = 0; kk < GBK; kk += 8) {
            uint32_t afr[4][4], bfr[4][2];
#pragma unroll
            for (int im = 0; im < 4; im++) {
                const int r = wm * 64 + im * 16 + gid;
                afr[im][0] = __float_as_uint(sA[cur + r * GSTR + kk + tig]);
                afr[im][1] = __float_as_uint(sA[cur + (r + 8) * GSTR + kk + tig]);
                afr[im][2] = __float_as_uint(sA[cur + r * GSTR + kk + tig + 4]);
                afr[im][3] = __float_as_uint(sA[cur + (r + 8) * GSTR + kk + tig + 4]);
            }
#pragma unroll
            for (int jn = 0; jn < 4; jn++) {
                const int n = wn * 32 + jn * 8 + gid;
                bfr[jn][0] = __float_as_uint(sB[cur + n * GSTR + kk + tig]);
                bfr[jn][1] = __float_as_uint(sB[cur + n * GSTR + kk + tig + 4]);
            }
#pragma unroll
            for (int im = 0; im < 4; im++)
#pragma unroll
                for (int jn = 0; jn < 4; jn++)
                    mma_tf32(acc[im][jn], afr[im], bfr[jn]);
        }

        if (t + 1 < ntiles) {
            const int nxt = ((t + 1) & 1) * GBUF;
#pragma unroll
            for (int i = 0; i < 4; i++) {
                const int r = lr0 + i * 32;
                float* da = &sA[nxt + r * GSTR + lc4];
                da[0] = to_tf32(pa[i].x); da[1] = to_tf32(pa[i].y);
                da[2] = to_tf32(pa[i].z); da[3] = to_tf32(pa[i].w);
                float* db = &sB[nxt + r * GSTR + lc4];
                db[0] = to_tf32(pb[i].x); db[1] = to_tf32(pb[i].y);
                db[2] = to_tf32(pb[i].z); db[3] = to_tf32(pb[i].w);
            }
        }
        __syncthreads();
    }

#pragma unroll
    for (int im = 0; im < 4; im++) {
#pragma unroll
        for (int jn = 0; jn < 4; jn++) {
            const int row = m0 + wm * 64 + im * 16 + gid;
            const int col = n0 + wn * 32 + jn * 8 + 2 * tig;
            *(float2*)&C[(size_t)row * N + col]       = make_float2(acc[im][jn][0], acc[im][jn][1]);
            *(float2*)&C[(size_t)(row + 8) * N + col] = make_float2(acc[im][jn][2], acc[im][jn][3]);
        }
    }
}

// ---------------------------------------------------------------------------
// Fused per-head LayerNorm + RoPE, in place. (unchanged)
// ---------------------------------------------------------------------------
__global__ void __launch_bounds__(128) norm_rope_kernel(
    float* __restrict__ x, const float* __restrict__ w,
    const int* __restrict__ pos_ids, int H)
{
    const int idx = blockIdx.x;
    const int h = idx % H;
    const int s = (idx / H) % SEQ;
    float* xp = x + (size_t)idx * HD;

    const int t = threadIdx.x;
    const int lane = t & 31, wid = t >> 5;

    __shared__ float red[4];
    __shared__ float sx[128];

    float v = xp[t];

    float sum = v;
#pragma unroll
    for (int o = 16; o; o >>= 1) sum += __shfl_xor_sync(~0u, sum, o);
    if (!lane) red[wid] = sum;
    __syncthreads();
    const float mean = (red[0] + red[1] + red[2] + red[3]) * (1.f / 128.f);

    const float d = v - mean;
    float s2 = d * d;
#pragma unroll
    for (int o = 16; o; o >>= 1) s2 += __shfl_xor_sync(~0u, s2, o);
    __syncthreads();
    if (!lane) red[wid] = s2;
    __syncthreads();
    const float var = (red[0] + red[1] + red[2] + red[3]) * (1.f / 128.f);

    const float xn = d * rsqrtf(var + 1e-5f) * w[h * HD + t];
    sx[t] = xn;
    __syncthreads();

    const int i = t & 63;
    const float ang = (float)pos_ids[s] * __expf(-(float)i * 0.14391156831212787f);
    float sn, cs;
    sincosf(ang, &sn, &cs);
    float out;
    if (t < 64) out = xn * cs - sx[t + 64] * sn;
    else        out = xn * cs + sx[t - 64] * sn;
    xp[t] = out;
}

// ---------------------------------------------------------------------------
// Tensor-core (tf32) causal flash attention.
// CTA: 128 q-rows, kv tiles of 64. 8 warps; warp w owns q-rows 16w..16w+15.
// Q: [B,S,NH,HD]  K,V: [B,S,NKV,HD]  O: [B,S,NH*HD]
// ---------------------------------------------------------------------------
#define FQSTR 132
#define FKSTR 132
#define FVSTR 68
#define FPSTR 68

__global__ void __launch_bounds__(256) flash_mma_kernel(
    const float* __restrict__ Q, const float* __restrict__ K,
    const float* __restrict__ V, float* __restrict__ O)
{
    extern __shared__ float sm[];
    float* sQ  = sm;                      // 128*132
    float* sK  = sQ + 128 * FQSTR;        // 64*132
    float* sVt = sK + 64 * FKSTR;         // 128*68  (V transposed: [d][kv])
    float* sP  = sVt + 128 * FVSTR;       // 128*68

    const int qt = blockIdx.x, h = blockIdx.y, b = blockIdx.z;
    const int kvh = h >> 2;
    const int tid = threadIdx.x, lane = tid & 31, w = tid >> 5;
    const int gid = lane >> 2, tig = lane & 3;
    const float scale = 0.08838834764831845f;   // 1/sqrt(128)

    // Load Q tile (128 x 128), scale folded in, tf32-rounded
    for (int i = tid; i < 128 * 32; i += 256) {
        const int r = i >> 5, c4 = (i & 31) << 2;
        float4 qv = *(const float4*)&Q[(((size_t)(b * SEQ + qt * 128 + r)) * NH + h) * HD + c4];
        float* d = &sQ[r * FQSTR + c4];
        d[0] = to_tf32(qv.x * scale); d[1] = to_tf32(qv.y * scale);
        d[2] = to_tf32(qv.z * scale); d[3] = to_tf32(qv.w * scale);
    }

    float m0 = -1e30f, m1 = -1e30f, l0 = 0.f, l1 = 0.f;
    float o[16][4];
#pragma unroll
    for (int t = 0; t < 16; t++)
#pragma unroll
        for (int c = 0; c < 4; c++) o[t][c] = 0.f;

    const int r0 = 16 * w + gid;           // local q-row (second row: r0+8)
    const int grow0 = qt * 128 + r0;
    const int grow1 = grow0 + 8;

    const int jmax = 2 * qt + 1;
    for (int j = 0; j <= jmax; j++) {
        __syncthreads();   // all warps done reading sK/sVt from previous iter

        // K tile (64 x 128), tf32
        for (int i = tid; i < 64 * 32; i += 256) {
            const int r = i >> 5, c4 = (i & 31) << 2;
            float4 kv = *(const float4*)&K[(((size_t)(b * SEQ + j * 64 + r)) * NKV + kvh) * HD + c4];
            float* d = &sK[r * FKSTR + c4];
            d[0] = to_tf32(kv.x); d[1] = to_tf32(kv.y);
            d[2] = to_tf32(kv.z); d[3] = to_tf32(kv.w);
        }
        // V tile transposed: sVt[d][kv], lane-spread rows -> conflict-free STS
        for (int i = tid; i < 64 * 32; i += 256) {
            const int r = i & 63, c4 = (i >> 6) << 2;
            float4 vv = *(const float4*)&V[(((size_t)(b * SEQ + j * 64 + r)) * NKV + kvh) * HD + c4];
            sVt[(c4 + 0) * FVSTR + r] = to_tf32(vv.x);
            sVt[(c4 + 1) * FVSTR + r] = to_tf32(vv.y);
            sVt[(c4 + 2) * FVSTR + r] = to_tf32(vv.z);
            sVt[(c4 + 3) * FVSTR + r] = to_tf32(vv.w);
        }
        __syncthreads();

        // S = Q K^T : warp rows 16w..16w+15, cols 0..63 (8 n-tiles)
        float sc[8][4];
#pragma unroll
        for (int t = 0; t < 8; t++)
#pragma unroll
            for (int c = 0; c < 4; c++) sc[t][c] = 0.f;

#pragma unroll
        for (int kk = 0; kk < 128; kk += 8) {
            uint32_t a[4];
            a[0] = __float_as_uint(sQ[r0 * FQSTR + kk + tig]);
            a[1] = __float_as_uint(sQ[(r0 + 8) * FQSTR + kk + tig]);
            a[2] = __float_as_uint(sQ[r0 * FQSTR + kk + tig + 4]);
            a[3] = __float_as_uint(sQ[(r0 + 8) * FQSTR + kk + tig + 4]);
#pragma unroll
            for (int t = 0; t < 8; t++) {
                uint32_t bf[2];
                bf[0] = __float_as_uint(sK[(8 * t + gid) * FKSTR + kk + tig]);
                bf[1] = __float_as_uint(sK[(8 * t + gid) * FKSTR + kk + tig + 4]);
                mma_tf32(sc[t], a, bf);
            }
        }

        // causal mask
        const int cb = j * 64 + 2 * tig;
#pragma unroll
        for (int t = 0; t < 8; t++) {
            const int c0 = cb + 8 * t, c1 = c0 + 1;
            if (c0 > grow0) sc[t][0] = -1e30f;
            if (c1 > grow0) sc[t][1] = -1e30f;
            if (c0 > grow1) sc[t][2] = -1e30f;
            if (c1 > grow1) sc[t][3] = -1e30f;
        }

        // online softmax (rows r0, r0+8); full row spread over 4 tig lanes
        float mx0 = -1e30f, mx1 = -1e30f;
#pragma unroll
        for (int t = 0; t < 8; t++) {
            mx0 = fmaxf(mx0, fmaxf(sc[t][0], sc[t][1]));
            mx1 = fmaxf(mx1, fmaxf(sc[t][2], sc[t][3]));
        }
        mx0 = fmaxf(mx0, __shfl_xor_sync(~0u, mx0, 1));
        mx0 = fmaxf(mx0, __shfl_xor_sync(~0u, mx0, 2));
        mx1 = fmaxf(mx1, __shfl_xor_sync(~0u, mx1, 1));
        mx1 = fmaxf(mx1, __shfl_xor_sync(~0u, mx1, 2));

        const float mn0 = fmaxf(m0, mx0), mn1 = fmaxf(m1, mx1);
        float rs0 = 0.f, rs1 = 0.f;
#pragma unroll
        for (int t = 0; t < 8; t++) {
            sc[t][0] = __expf(sc[t][0] - mn0);
            sc[t][1] = __expf(sc[t][1] - mn0);
            sc[t][2] = __expf(sc[t][2] - mn1);
            sc[t][3] = __expf(sc[t][3] - mn1);
            rs0 += sc[t][0] + sc[t][1];
            rs1 += sc[t][2] + sc[t][3];
        }
        rs0 += __shfl_xor_sync(~0u, rs0, 1); rs0 += __shfl_xor_sync(~0u, rs0, 2);
        rs1 += __shfl_xor_sync(~0u, rs1, 1); rs1 += __shfl_xor_sync(~0u, rs1, 2);

        const float al0 = __expf(m0 - mn0), al1 = __expf(m1 - mn1);
        l0 = l0 * al0 + rs0;  l1 = l1 * al1 + rs1;
        m0 = mn0;  m1 = mn1;

#pragma unroll
        for (int t = 0; t < 16; t++) {
            o[t][0] *= al0; o[t][1] *= al0;
            o[t][2] *= al1; o[t][3] *= al1;
        }

        // store P (tf32) to warp-private rows of sP
#pragma unroll
        for (int t = 0; t < 8; t++) {
            const int c = 8 * t + 2 * tig;
            sP[r0 * FPSTR + c]           = to_tf32(sc[t][0]);
            sP[r0 * FPSTR + c + 1]       = to_tf32(sc[t][1]);
            sP[(r0 + 8) * FPSTR + c]     = to_tf32(sc[t][2]);
            sP[(r0 + 8) * FPSTR + c + 1] = to_tf32(sc[t][3]);
        }
        __syncwarp();

        // O += P @ V : 16 n-tiles over d=128, k = kv (64)
#pragma unroll
        for (int kk = 0; kk < 64; kk += 8) {
            uint32_t a[4];
            a[0] = __float_as_uint(sP[r0 * FPSTR + kk + tig]);
            a[1] = __float_as_uint(sP[(r0 + 8) * FPSTR + kk + tig]);
            a[2] = __float_as_uint(sP[r0 * FPSTR + kk + tig + 4]);
            a[3] = __float_as_uint(sP[(r0 + 8) * FPSTR + kk + tig + 4]);
#pragma unroll
            for (int t = 0; t < 16; t++) {
                uint32_t bf[2];
                bf[0] = __float_as_uint(sVt[(8 * t + gid) * FVSTR + kk + tig]);
                bf[1] = __float_as_uint(sVt[(8 * t + gid) * FVSTR + kk + tig + 4]);
                mma_tf32(o[t], a, bf);
            }
        }
    }

    // epilogue: normalize and write O[b, s, h*128 + d]
    const float i0 = 1.f / l0, i1 = 1.f / l1;
#pragma unroll
    for (int t = 0; t < 16; t++) {
        const int col = 8 * t + 2 * tig;
        float* d0 = &O[(((size_t)(b * SEQ + qt * 128 + r0)) * NH + h) * HD + col];
        float* d1 = &O[(((size_t)(b * SEQ + qt * 128 + r0 + 8)) * NH + h) * HD + col];
        *(float2*)d0 = make_float2(o[t][0] * i0, o[t][1] * i0);
        *(float2*)d1 = make_float2(o[t][2] * i1, o[t][3] * i1);
    }
}

// ---------------------------------------------------------------------------
extern "C" void kernel_launch(void* const* d_in, const int* in_sizes, int n_in,
                              void* d_out, int out_size)
{
    const float* hs = (const float*)d_in[0];
    const int*   pos = (const int*)d_in[1];
    const float* wq = (const float*)d_in[2];
    const float* wk = (const float*)d_in[3];
    const float* wv = (const float*)d_in[4];
    const float* wo = (const float*)d_in[5];
    const float* qn = (const float*)d_in[6];
    const float* kn = (const float*)d_in[7];
    float* out = (float*)d_out;

    float *q, *k, *v, *attn;
    cudaGetSymbolAddress((void**)&q, g_q);
    cudaGetSymbolAddress((void**)&k, g_k);
    cudaGetSymbolAddress((void**)&v, g_v);
    cudaGetSymbolAddress((void**)&attn, g_attn);

    const size_t gemm_smem = (size_t)4 * GBUF * sizeof(float);  // 81920 B
    cudaFuncSetAttribute(gemm_tf32_kernel,
                         cudaFuncAttributeMaxDynamicSharedMemorySize, (int)gemm_smem);

    const size_t fa_smem = (size_t)(128 * FQSTR + 64 * FKSTR + 128 * FVSTR + 128 * FPSTR) * sizeof(float);
    cudaFuncSetAttribute(flash_mma_kernel,
                         cudaFuncAttributeMaxDynamicSharedMemorySize, (int)fa_smem);

    // QKV projections (tensor cores, tf32)
    gemm_tf32_kernel<<<dim3(NH * HD / 128, MTOT / 128), 256, gemm_smem>>>(hs, wq, q, MTOT, NH * HD, HIDDEN);
    gemm_tf32_kernel<<<dim3(NKV * HD / 128, MTOT / 128), 256, gemm_smem>>>(hs, wk, k, MTOT, NKV * HD, HIDDEN);
    gemm_tf32_kernel<<<dim3(NKV * HD / 128, MTOT / 128), 256, gemm_smem>>>(hs, wv, v, MTOT, NKV * HD, HIDDEN);

    // Per-head LN + RoPE (in place)
    norm_rope_kernel<<<MTOT * NH, 128>>>(q, qn, pos, NH);
    norm_rope_kernel<<<MTOT * NKV, 128>>>(k, kn, pos, NKV);

    // Causal flash attention (tensor cores, tf32)
    flash_mma_kernel<<<dim3(SEQ / 128, NH, BATCH), 256, fa_smem>>>(q, k, v, attn);

    // Output projection (tensor cores, tf32)
    gemm_tf32_kernel<<<dim3(HIDDEN / 128, MTOT / 128), 256, gemm_smem>>>(attn, wo, out, MTOT, HIDDEN, HIDDEN);
}

// round 7
// speedup vs baseline: 3.2344x; 1.3248x over previous
#include <cuda_runtime.h>
#include <math.h>
#include <stdint.h>

#define HIDDEN 4096
#define NH 32
#define NKV 8
#define HD 128
#define BATCH 2
#define SEQ 2048
#define MTOT (BATCH*SEQ)

// Scratch (allocation-free rule: __device__ globals)
__device__ float g_q[(size_t)MTOT * NH * HD];     // 64 MB
__device__ float g_k[(size_t)MTOT * NKV * HD];    // 16 MB
__device__ float g_v[(size_t)MTOT * NKV * HD];    // 16 MB
__device__ float g_attn[(size_t)MTOT * NH * HD];  // 64 MB

// ---------------------------------------------------------------------------
// tf32 / async helpers
// ---------------------------------------------------------------------------
__device__ __forceinline__ float to_tf32(float x) {
    uint32_t u;
    asm("cvt.rna.tf32.f32 %0, %1;" : "=r"(u) : "f"(x));
    return __uint_as_float(u);
}
__device__ __forceinline__ uint32_t to_tf32_u(float x) {
    uint32_t u;
    asm("cvt.rna.tf32.f32 %0, %1;" : "=r"(u) : "f"(x));
    return u;
}

__device__ __forceinline__ void mma_tf32(float* c, const uint32_t* a, const uint32_t* b) {
    asm volatile(
        "mma.sync.aligned.m16n8k8.row.col.f32.tf32.tf32.f32 "
        "{%0,%1,%2,%3}, {%4,%5,%6,%7}, {%8,%9}, {%0,%1,%2,%3};"
        : "+f"(c[0]), "+f"(c[1]), "+f"(c[2]), "+f"(c[3])
        : "r"(a[0]), "r"(a[1]), "r"(a[2]), "r"(a[3]), "r"(b[0]), "r"(b[1]));
}

__device__ __forceinline__ void cp_async16(float* smem_ptr, const float* gptr) {
    uint32_t saddr = (uint32_t)__cvta_generic_to_shared(smem_ptr);
    asm volatile("cp.async.cg.shared.global [%0], [%1], 16;" :: "r"(saddr), "l"(gptr));
}
__device__ __forceinline__ void cp_commit() {
    asm volatile("cp.async.commit_group;");
}
template <int N>
__device__ __forceinline__ void cp_wait() {
    asm volatile("cp.async.wait_group %0;" :: "n"(N));
}

// ---------------------------------------------------------------------------
// tf32 tensor-core GEMM: C[M,N] = A[M,K] @ W[N,K]^T
// CTA tile 128x128, BK=32, 256 threads (8 warps), warp tile 64x32.
// cp.async 2-stage pipeline, raw fp32 in smem, cvt.rna at fragment load.
// 2 CTAs/SM (smem 72KB/CTA, regs capped by launch_bounds).
// ---------------------------------------------------------------------------
#define GBM 128
#define GBN 128
#define GBK 32
#define GSTR 36
#define GBUF (128*GSTR)

__global__ void __launch_bounds__(256, 2) gemm_tf32_kernel(
    const float* __restrict__ A, const float* __restrict__ W,
    float* __restrict__ C, int M, int N, int K)
{
    extern __shared__ float sm[];
    // stage s: A at sm + s*2*GBUF, B at sm + s*2*GBUF + GBUF

    const int tid  = threadIdx.x;
    const int lane = tid & 31;
    const int wid  = tid >> 5;
    const int wm   = wid & 1;
    const int wn   = wid >> 1;
    const int gid  = lane >> 2;
    const int tig  = lane & 3;

    const int m0 = blockIdx.y * GBM;
    const int n0 = blockIdx.x * GBN;

    const int lr0 = tid >> 3;            // row 0..31 (+32 per step)
    const int lc4 = (tid & 7) << 2;      // k offset 0,4,..28

    float acc[4][4][4];
#pragma unroll
    for (int i = 0; i < 4; i++)
#pragma unroll
        for (int j = 0; j < 4; j++)
#pragma unroll
            for (int c = 0; c < 4; c++) acc[i][j][c] = 0.f;

    // prologue: async load tile 0 into stage 0
    {
        float* sA = sm;
        float* sB = sm + GBUF;
#pragma unroll
        for (int i = 0; i < 4; i++) {
            const int r = lr0 + i * 32;
            cp_async16(&sA[r * GSTR + lc4], &A[(size_t)(m0 + r) * K + lc4]);
            cp_async16(&sB[r * GSTR + lc4], &W[(size_t)(n0 + r) * K + lc4]);
        }
        cp_commit();
    }

    const int ntiles = K / GBK;
    for (int t = 0; t < ntiles; t++) {
        const int cur = (t & 1) * 2 * GBUF;

        // issue async loads for tile t+1 into the other stage
        if (t + 1 < ntiles) {
            const int nxt = ((t + 1) & 1) * 2 * GBUF;
            float* sA = sm + nxt;
            float* sB = sm + nxt + GBUF;
            const size_t k0 = (size_t)(t + 1) * GBK;
#pragma unroll
            for (int i = 0; i < 4; i++) {
                const int r = lr0 + i * 32;
                cp_async16(&sA[r * GSTR + lc4], &A[(size_t)(m0 + r) * K + k0 + lc4]);
                cp_async16(&sB[r * GSTR + lc4], &W[(size_t)(n0 + r) * K + k0 + lc4]);
            }
            cp_commit();
            cp_wait<1>();   // tile t complete (t+1 may still be in flight)
        } else {
            cp_wait<0>();
        }
        __syncthreads();

        const float* sA = sm + cur;
        const float* sB = sm + cur + GBUF;

        // compute: 4 k-steps of 8; cvt.rna applied at fragment load
#pragma unroll
        for (int kk = 0; kk < GBK; kk += 8) {
            uint32_t afr[4][4], bfr[4][2];
#pragma unroll
            for (int im = 0; im < 4; im++) {
                const int r = wm * 64 + im * 16 + gid;
                afr[im][0] = to_tf32_u(sA[r * GSTR + kk + tig]);
                afr[im][1] = to_tf32_u(sA[(r + 8) * GSTR + kk + tig]);
                afr[im][2] = to_tf32_u(sA[r * GSTR + kk + tig + 4]);
                afr[im][3] = to_tf32_u(sA[(r + 8) * GSTR + kk + tig + 4]);
            }
#pragma unroll
            for (int jn = 0; jn < 4; jn++) {
                const int n = wn * 32 + jn * 8 + gid;
                bfr[jn][0] = to_tf32_u(sB[n * GSTR + kk + tig]);
                bfr[jn][1] = to_tf32_u(sB[n * GSTR + kk + tig + 4]);
            }
#pragma unroll
            for (int im = 0; im < 4; im++)
#pragma unroll
                for (int jn = 0; jn < 4; jn++)
                    mma_tf32(acc[im][jn], afr[im], bfr[jn]);
        }
        __syncthreads();   // done reading cur; next iter may overwrite it
    }

    // epilogue
#pragma unroll
    for (int im = 0; im < 4; im++) {
#pragma unroll
        for (int jn = 0; jn < 4; jn++) {
            const int row = m0 + wm * 64 + im * 16 + gid;
            const int col = n0 + wn * 32 + jn * 8 + 2 * tig;
            *(float2*)&C[(size_t)row * N + col]       = make_float2(acc[im][jn][0], acc[im][jn][1]);
            *(float2*)&C[(size_t)(row + 8) * N + col] = make_float2(acc[im][jn][2], acc[im][jn][3]);
        }
    }
}

// ---------------------------------------------------------------------------
// Fused per-head LayerNorm + RoPE, in place. (unchanged)
// ---------------------------------------------------------------------------
__global__ void __launch_bounds__(128) norm_rope_kernel(
    float* __restrict__ x, const float* __restrict__ w,
    const int* __restrict__ pos_ids, int H)
{
    const int idx = blockIdx.x;
    const int h = idx % H;
    const int s = (idx / H) % SEQ;
    float* xp = x + (size_t)idx * HD;

    const int t = threadIdx.x;
    const int lane = t & 31, wid = t >> 5;

    __shared__ float red[4];
    __shared__ float sx[128];

    float v = xp[t];

    float sum = v;
#pragma unroll
    for (int o = 16; o; o >>= 1) sum += __shfl_xor_sync(~0u, sum, o);
    if (!lane) red[wid] = sum;
    __syncthreads();
    const float mean = (red[0] + red[1] + red[2] + red[3]) * (1.f / 128.f);

    const float d = v - mean;
    float s2 = d * d;
#pragma unroll
    for (int o = 16; o; o >>= 1) s2 += __shfl_xor_sync(~0u, s2, o);
    __syncthreads();
    if (!lane) red[wid] = s2;
    __syncthreads();
    const float var = (red[0] + red[1] + red[2] + red[3]) * (1.f / 128.f);

    const float xn = d * rsqrtf(var + 1e-5f) * w[h * HD + t];
    sx[t] = xn;
    __syncthreads();

    const int i = t & 63;
    const float ang = (float)pos_ids[s] * __expf(-(float)i * 0.14391156831212787f);
    float sn, cs;
    sincosf(ang, &sn, &cs);
    float out;
    if (t < 64) out = xn * cs - sx[t + 64] * sn;
    else        out = xn * cs + sx[t - 64] * sn;
    xp[t] = out;
}

// ---------------------------------------------------------------------------
// Tensor-core (tf32) causal flash attention. (unchanged from R5)
// ---------------------------------------------------------------------------
#define FQSTR 132
#define FKSTR 132
#define FVSTR 68
#define FPSTR 68

__global__ void __launch_bounds__(256) flash_mma_kernel(
    const float* __restrict__ Q, const float* __restrict__ K,
    const float* __restrict__ V, float* __restrict__ O)
{
    extern __shared__ float sm[];
    float* sQ  = sm;                      // 128*132
    float* sK  = sQ + 128 * FQSTR;        // 64*132
    float* sVt = sK + 64 * FKSTR;         // 128*68  (V transposed: [d][kv])
    float* sP  = sVt + 128 * FVSTR;       // 128*68

    const int qt = blockIdx.x, h = blockIdx.y, b = blockIdx.z;
    const int kvh = h >> 2;
    const int tid = threadIdx.x, lane = tid & 31, w = tid >> 5;
    const int gid = lane >> 2, tig = lane & 3;
    const float scale = 0.08838834764831845f;   // 1/sqrt(128)

    for (int i = tid; i < 128 * 32; i += 256) {
        const int r = i >> 5, c4 = (i & 31) << 2;
        float4 qv = *(const float4*)&Q[(((size_t)(b * SEQ + qt * 128 + r)) * NH + h) * HD + c4];
        float* d = &sQ[r * FQSTR + c4];
        d[0] = to_tf32(qv.x * scale); d[1] = to_tf32(qv.y * scale);
        d[2] = to_tf32(qv.z * scale); d[3] = to_tf32(qv.w * scale);
    }

    float m0 = -1e30f, m1 = -1e30f, l0 = 0.f, l1 = 0.f;
    float o[16][4];
#pragma unroll
    for (int t = 0; t < 16; t++)
#pragma unroll
        for (int c = 0; c < 4; c++) o[t][c] = 0.f;

    const int r0 = 16 * w + gid;
    const int grow0 = qt * 128 + r0;
    const int grow1 = grow0 + 8;

    const int jmax = 2 * qt + 1;
    for (int j = 0; j <= jmax; j++) {
        __syncthreads();

        for (int i = tid; i < 64 * 32; i += 256) {
            const int r = i >> 5, c4 = (i & 31) << 2;
            float4 kv = *(const float4*)&K[(((size_t)(b * SEQ + j * 64 + r)) * NKV + kvh) * HD + c4];
            float* d = &sK[r * FKSTR + c4];
            d[0] = to_tf32(kv.x); d[1] = to_tf32(kv.y);
            d[2] = to_tf32(kv.z); d[3] = to_tf32(kv.w);
        }
        for (int i = tid; i < 64 * 32; i += 256) {
            const int r = i & 63, c4 = (i >> 6) << 2;
            float4 vv = *(const float4*)&V[(((size_t)(b * SEQ + j * 64 + r)) * NKV + kvh) * HD + c4];
            sVt[(c4 + 0) * FVSTR + r] = to_tf32(vv.x);
            sVt[(c4 + 1) * FVSTR + r] = to_tf32(vv.y);
            sVt[(c4 + 2) * FVSTR + r] = to_tf32(vv.z);
            sVt[(c4 + 3) * FVSTR + r] = to_tf32(vv.w);
        }
        __syncthreads();

        float sc[8][4];
#pragma unroll
        for (int t = 0; t < 8; t++)
#pragma unroll
            for (int c = 0; c < 4; c++) sc[t][c] = 0.f;

#pragma unroll
        for (int kk = 0; kk < 128; kk += 8) {
            uint32_t a[4];
            a[0] = __float_as_uint(sQ[r0 * FQSTR + kk + tig]);
            a[1] = __float_as_uint(sQ[(r0 + 8) * FQSTR + kk + tig]);
            a[2] = __float_as_uint(sQ[r0 * FQSTR + kk + tig + 4]);
            a[3] = __float_as_uint(sQ[(r0 + 8) * FQSTR + kk + tig + 4]);
#pragma unroll
            for (int t = 0; t < 8; t++) {
                uint32_t bf[2];
                bf[0] = __float_as_uint(sK[(8 * t + gid) * FKSTR + kk + tig]);
                bf[1] = __float_as_uint(sK[(8 * t + gid) * FKSTR + kk + tig + 4]);
                mma_tf32(sc[t], a, bf);
            }
        }

        const int cb = j * 64 + 2 * tig;
#pragma unroll
        for (int t = 0; t < 8; t++) {
            const int c0 = cb + 8 * t, c1 = c0 + 1;
            if (c0 > grow0) sc[t][0] = -1e30f;
            if (c1 > grow0) sc[t][1] = -1e30f;
            if (c0 > grow1) sc[t][2] = -1e30f;
            if (c1 > grow1) sc[t][3] = -1e30f;
        }

        float mx0 = -1e30f, mx1 = -1e30f;
#pragma unroll
        for (int t = 0; t < 8; t++) {
            mx0 = fmaxf(mx0, fmaxf(sc[t][0], sc[t][1]));
            mx1 = fmaxf(mx1, fmaxf(sc[t][2], sc[t][3]));
        }
        mx0 = fmaxf(mx0, __shfl_xor_sync(~0u, mx0, 1));
        mx0 = fmaxf(mx0, __shfl_xor_sync(~0u, mx0, 2));
        mx1 = fmaxf(mx1, __shfl_xor_sync(~0u, mx1, 1));
        mx1 = fmaxf(mx1, __shfl_xor_sync(~0u, mx1, 2));

        const float mn0 = fmaxf(m0, mx0), mn1 = fmaxf(m1, mx1);
        float rs0 = 0.f, rs1 = 0.f;
#pragma unroll
        for (int t = 0; t < 8; t++) {
            sc[t][0] = __expf(sc[t][0] - mn0);
            sc[t][1] = __expf(sc[t][1] - mn0);
            sc[t][2] = __expf(sc[t][2] - mn1);
            sc[t][3] = __expf(sc[t][3] - mn1);
            rs0 += sc[t][0] + sc[t][1];
            rs1 += sc[t][2] + sc[t][3];
        }
        rs0 += __shfl_xor_sync(~0u, rs0, 1); rs0 += __shfl_xor_sync(~0u, rs0, 2);
        rs1 += __shfl_xor_sync(~0u, rs1, 1); rs1 += __shfl_xor_sync(~0u, rs1, 2);

        const float al0 = __expf(m0 - mn0), al1 = __expf(m1 - mn1);
        l0 = l0 * al0 + rs0;  l1 = l1 * al1 + rs1;
        m0 = mn0;  m1 = mn1;

#pragma unroll
        for (int t = 0; t < 16; t++) {
            o[t][0] *= al0; o[t][1] *= al0;
            o[t][2] *= al1; o[t][3] *= al1;
        }

#pragma unroll
        for (int t = 0; t < 8; t++) {
            const int c = 8 * t + 2 * tig;
            sP[r0 * FPSTR + c]           = to_tf32(sc[t][0]);
            sP[r0 * FPSTR + c + 1]       = to_tf32(sc[t][1]);
            sP[(r0 + 8) * FPSTR + c]     = to_tf32(sc[t][2]);
            sP[(r0 + 8) * FPSTR + c + 1] = to_tf32(sc[t][3]);
        }
        __syncwarp();

#pragma unroll
        for (int kk = 0; kk < 64; kk += 8) {
            uint32_t a[4];
            a[0] = __float_as_uint(sP[r0 * FPSTR + kk + tig]);
            a[1] = __float_as_uint(sP[(r0 + 8) * FPSTR + kk + tig]);
            a[2] = __float_as_uint(sP[r0 * FPSTR + kk + tig + 4]);
            a[3] = __float_as_uint(sP[(r0 + 8) * FPSTR + kk + tig + 4]);
#pragma unroll
            for (int t = 0; t < 16; t++) {
                uint32_t bf[2];
                bf[0] = __float_as_uint(sVt[(8 * t + gid) * FVSTR + kk + tig]);
                bf[1] = __float_as_uint(sVt[(8 * t + gid) * FVSTR + kk + tig + 4]);
                mma_tf32(o[t], a, bf);
            }
        }
    }

    const float i0 = 1.f / l0, i1 = 1.f / l1;
#pragma unroll
    for (int t = 0; t < 16; t++) {
        const int col = 8 * t + 2 * tig;
        float* d0 = &O[(((size_t)(b * SEQ + qt * 128 + r0)) * NH + h) * HD + col];
        float* d1 = &O[(((size_t)(b * SEQ + qt * 128 + r0 + 8)) * NH + h) * HD + col];
        *(float2*)d0 = make_float2(o[t][0] * i0, o[t][1] * i0);
        *(float2*)d1 = make_float2(o[t][2] * i1, o[t][3] * i1);
    }
}

// ---------------------------------------------------------------------------
extern "C" void kernel_launch(void* const* d_in, const int* in_sizes, int n_in,
                              void* d_out, int out_size)
{
    const float* hs = (const float*)d_in[0];
    const int*   pos = (const int*)d_in[1];
    const float* wq = (const float*)d_in[2];
    const float* wk = (const float*)d_in[3];
    const float* wv = (const float*)d_in[4];
    const float* wo = (const float*)d_in[5];
    const float* qn = (const float*)d_in[6];
    const float* kn = (const float*)d_in[7];
    float* out = (float*)d_out;

    float *q, *k, *v, *attn;
    cudaGetSymbolAddress((void**)&q, g_q);
    cudaGetSymbolAddress((void**)&k, g_k);
    cudaGetSymbolAddress((void**)&v, g_v);
    cudaGetSymbolAddress((void**)&attn, g_attn);

    const size_t gemm_smem = (size_t)4 * GBUF * sizeof(float);  // 73728 B
    cudaFuncSetAttribute(gemm_tf32_kernel,
                         cudaFuncAttributeMaxDynamicSharedMemorySize, (int)gemm_smem);

    const size_t fa_smem = (size_t)(128 * FQSTR + 64 * FKSTR + 128 * FVSTR + 128 * FPSTR) * sizeof(float);
    cudaFuncSetAttribute(flash_mma_kernel,
                         cudaFuncAttributeMaxDynamicSharedMemorySize, (int)fa_smem);

    // QKV projections (tensor cores, tf32, cp.async pipeline)
    gemm_tf32_kernel<<<dim3(NH * HD / 128, MTOT / 128), 256, gemm_smem>>>(hs, wq, q, MTOT, NH * HD, HIDDEN);
    gemm_tf32_kernel<<<dim3(NKV * HD / 128, MTOT / 128), 256, gemm_smem>>>(hs, wk, k, MTOT, NKV * HD, HIDDEN);
    gemm_tf32_kernel<<<dim3(NKV * HD / 128, MTOT / 128), 256, gemm_smem>>>(hs, wv, v, MTOT, NKV * HD, HIDDEN);

    // Per-head LN + RoPE (in place)
    norm_rope_kernel<<<MTOT * NH, 128>>>(q, qn, pos, NH);
    norm_rope_kernel<<<MTOT * NKV, 128>>>(k, kn, pos, NKV);

    // Causal flash attention (tensor cores, tf32)
    flash_mma_kernel<<<dim3(SEQ / 128, NH, BATCH), 256, fa_smem>>>(q, k, v, attn);

    // Output projection (tensor cores, tf32)
    gemm_tf32_kernel<<<dim3(HIDDEN / 128, MTOT / 128), 256, gemm_smem>>>(attn, wo, out, MTOT, HIDDEN, HIDDEN);
}

// round 17
// speedup vs baseline: 6.0345x; 1.8657x over previous
#include <cuda_runtime.h>
#include <cuda_fp16.h>
#include <math.h>
#include <stdint.h>

#define HIDDEN 4096
#define NH 32
#define NKV 8
#define HD 128
#define BATCH 2
#define SEQ 2048
#define MTOT (BATCH*SEQ)

// Scratch (allocation-free rule: __device__ globals)
__device__ float  g_q[(size_t)MTOT * NH * HD];
__device__ float  g_k[(size_t)MTOT * NKV * HD];
__device__ float  g_v[(size_t)MTOT * NKV * HD];
__device__ __half g_attn[(size_t)MTOT * NH * HD];
// fp16 copies of GEMM inputs
__device__ __half g_hsh[(size_t)MTOT * HIDDEN];
__device__ __half g_wqh[(size_t)NH * HD * HIDDEN];
__device__ __half g_wkh[(size_t)NKV * HD * HIDDEN];
__device__ __half g_wvh[(size_t)NKV * HD * HIDDEN];
__device__ __half g_woh[(size_t)HIDDEN * NH * HD];

// ---------------------------------------------------------------------------
// helpers
// ---------------------------------------------------------------------------
__device__ __forceinline__ void mma_f16(float* c, const uint32_t* a, const uint32_t* b) {
    asm volatile(
        "mma.sync.aligned.m16n8k16.row.col.f32.f16.f16.f32 "
        "{%0,%1,%2,%3}, {%4,%5,%6,%7}, {%8,%9}, {%0,%1,%2,%3};"
        : "+f"(c[0]), "+f"(c[1]), "+f"(c[2]), "+f"(c[3])
        : "r"(a[0]), "r"(a[1]), "r"(a[2]), "r"(a[3]), "r"(b[0]), "r"(b[1]));
}

__device__ __forceinline__ void cp_async16(void* smem_ptr, const void* gptr) {
    uint32_t saddr = (uint32_t)__cvta_generic_to_shared(smem_ptr);
    asm volatile("cp.async.cg.shared.global [%0], [%1], 16;" :: "r"(saddr), "l"(gptr));
}
__device__ __forceinline__ void cp_commit() {
    asm volatile("cp.async.commit_group;");
}
template <int N>
__device__ __forceinline__ void cp_wait() {
    asm volatile("cp.async.wait_group %0;" :: "n"(N));
}

// ---------------------------------------------------------------------------
// f32 -> f16 conversion pass (4 elements / thread)
// ---------------------------------------------------------------------------
__global__ void __launch_bounds__(256) cvt_f16_kernel(
    const float* __restrict__ in, __half* __restrict__ out)
{
    const int i = blockIdx.x * 256 + threadIdx.x;
    float4 v = ((const float4*)in)[i];
    ((__half2*)out)[2 * i]     = __floats2half2_rn(v.x, v.y);
    ((__half2*)out)[2 * i + 1] = __floats2half2_rn(v.z, v.w);
}

// ---------------------------------------------------------------------------
// fp16 tensor-core GEMM: C[M,N] = A[M,K] @ W[N,K]^T   (A, W are fp16)
// CTA tile 128x128, BK=64 halves, 256 threads (8 warps), warp tile 64x32.
// 3-stage cp.async pipeline; 2 CTAs/SM.
// m16n8k16 fragments (gid=lane>>2, tig=lane&3):
//   a0={A[gid][2tig..+1]}(k<8) a1={A[gid+8]..} a2/a3 same at k+8
//   b0={W[n=gid][2tig..+1]}    b1 at k+8
//   c0=(gid,2tig) c1=(gid,2tig+1) c2=(gid+8,2tig) c3=(gid+8,2tig+1)
// ---------------------------------------------------------------------------
#define GBK 64
#define GSTRH 72                     // halves per smem row
#define GPW 36                       // words per smem row
#define GOPH (128*GSTRH)             // halves per operand tile (9216)
#define GSTAGEH (2*GOPH)             // halves per stage (A+B)

__global__ void __launch_bounds__(256, 2) gemm_f16_kernel(
    const __half* __restrict__ A, const __half* __restrict__ W,
    float* __restrict__ C, int M, int N, int K)
{
    extern __shared__ __half sh[];   // 3 stages

    const int tid  = threadIdx.x;
    const int lane = tid & 31;
    const int wid  = tid >> 5;
    const int wm   = wid & 1;
    const int wn   = wid >> 1;
    const int gid  = lane >> 2;
    const int tig  = lane & 3;

    const int m0 = blockIdx.y * 128;
    const int n0 = blockIdx.x * 128;

    float acc[4][4][4];
#pragma unroll
    for (int i = 0; i < 4; i++)
#pragma unroll
        for (int j = 0; j < 4; j++)
#pragma unroll
            for (int c = 0; c < 4; c++) acc[i][j][c] = 0.f;

    // load one operand k-tile (128 rows x 64 halves) : 1024 x 16B chunks
    auto load_tile = [&](const __half* __restrict__ G, int row0, int k0, __half* s) {
#pragma unroll
        for (int i = 0; i < 4; i++) {
            const int chunk = tid + (i << 8);
            const int r  = chunk >> 3;
            const int c8 = (chunk & 7) << 3;   // halves
            cp_async16(&s[r * GSTRH + c8], &G[(size_t)(row0 + r) * K + k0 + c8]);
        }
    };

    const int NT = K / GBK;

    // prologue: tiles 0, 1
    load_tile(A, m0, 0, sh);
    load_tile(W, n0, 0, sh + GOPH);
    cp_commit();
    load_tile(A, m0, GBK, sh + GSTAGEH);
    load_tile(W, n0, GBK, sh + GSTAGEH + GOPH);
    cp_commit();

    for (int t = 0; t < NT; t++) {
        if (t + 2 < NT) {
            __half* s = sh + ((t + 2) % 3) * GSTAGEH;
            load_tile(A, m0, (t + 2) * GBK, s);
            load_tile(W, n0, (t + 2) * GBK, s + GOPH);
            cp_commit();
            cp_wait<2>();
        } else if (t + 1 < NT) {
            cp_wait<1>();
        } else {
            cp_wait<0>();
        }
        __syncthreads();

        const uint32_t* sA = (const uint32_t*)(sh + (t % 3) * GSTAGEH);
        const uint32_t* sB = sA + GOPH / 2;

#pragma unroll
        for (int kk = 0; kk < GBK; kk += 16) {
            const int kw = kk >> 1;
            uint32_t afr[4][4], bfr[4][2];
#pragma unroll
            for (int im = 0; im < 4; im++) {
                const int r = wm * 64 + im * 16 + gid;
                afr[im][0] = sA[r * GPW + kw + tig];
                afr[im][1] = sA[(r + 8) * GPW + kw + tig];
                afr[im][2] = sA[r * GPW + kw + 4 + tig];
                afr[im][3] = sA[(r + 8) * GPW + kw + 4 + tig];
            }
#pragma unroll
            for (int jn = 0; jn < 4; jn++) {
                const int n = wn * 32 + jn * 8 + gid;
                bfr[jn][0] = sB[n * GPW + kw + tig];
                bfr[jn][1] = sB[n * GPW + kw + 4 + tig];
            }
#pragma unroll
            for (int im = 0; im < 4; im++)
#pragma unroll
                for (int jn = 0; jn < 4; jn++)
                    mma_f16(acc[im][jn], afr[im], bfr[jn]);
        }
        __syncthreads();
    }

#pragma unroll
    for (int im = 0; im < 4; im++) {
#pragma unroll
        for (int jn = 0; jn < 4; jn++) {
            const int row = m0 + wm * 64 + im * 16 + gid;
            const int col = n0 + wn * 32 + jn * 8 + 2 * tig;
            *(float2*)&C[(size_t)row * N + col]       = make_float2(acc[im][jn][0], acc[im][jn][1]);
            *(float2*)&C[(size_t)(row + 8) * N + col] = make_float2(acc[im][jn][2], acc[im][jn][3]);
        }
    }
}

// ---------------------------------------------------------------------------
// Fused per-head LayerNorm + RoPE, in place (fp32, unchanged).
// ---------------------------------------------------------------------------
__global__ void __launch_bounds__(128) norm_rope_kernel(
    float* __restrict__ x, const float* __restrict__ w,
    const int* __restrict__ pos_ids, int H)
{
    const int idx = blockIdx.x;
    const int h = idx % H;
    const int s = (idx / H) % SEQ;
    float* xp = x + (size_t)idx * HD;

    const int t = threadIdx.x;
    const int lane = t & 31, wid = t >> 5;

    __shared__ float red[4];
    __shared__ float sx[128];

    float v = xp[t];

    float sum = v;
#pragma unroll
    for (int o = 16; o; o >>= 1) sum += __shfl_xor_sync(~0u, sum, o);
    if (!lane) red[wid] = sum;
    __syncthreads();
    const float mean = (red[0] + red[1] + red[2] + red[3]) * (1.f / 128.f);

    const float d = v - mean;
    float s2 = d * d;
#pragma unroll
    for (int o = 16; o; o >>= 1) s2 += __shfl_xor_sync(~0u, s2, o);
    __syncthreads();
    if (!lane) red[wid] = s2;
    __syncthreads();
    const float var = (red[0] + red[1] + red[2] + red[3]) * (1.f / 128.f);

    const float xn = d * rsqrtf(var + 1e-5f) * w[h * HD + t];
    sx[t] = xn;
    __syncthreads();

    const int i = t & 63;
    const float ang = (float)pos_ids[s] * __expf(-(float)i * 0.14391156831212787f);
    float sn, cs;
    sincosf(ang, &sn, &cs);
    float out;
    if (t < 64) out = xn * cs - sx[t + 64] * sn;
    else        out = xn * cs + sx[t - 64] * sn;
    xp[t] = out;
}

// ---------------------------------------------------------------------------
// fp16 tensor-core causal flash attention (m16n8k16, fp32 softmax/accum).
// CTA: 128 q-rows, kv tiles of 64. 8 warps; warp w owns q-rows 16w..16w+15.
// Q,K,V fp32 in gmem (converted at smem store). O written as fp16.
// ---------------------------------------------------------------------------
#define FQW 68    // words (half2) per sQ/sK row (136 halves)
#define FVW 36    // words per sVt/sP row (72 halves)

__global__ void __launch_bounds__(256) flash_f16_kernel(
    const float* __restrict__ Q, const float* __restrict__ K,
    const float* __restrict__ V, __half* __restrict__ O)
{
    extern __shared__ char smc[];
    __half* sQ  = (__half*)smc;              // 128*136
    __half* sK  = sQ + 128 * 136;            // 64*136
    __half* sVt = sK + 64 * 136;             // 128*72  [d][kv]
    __half* sP  = sVt + 128 * 72;            // 128*72

    __half2* sQ2  = (__half2*)sQ;
    __half2* sK2  = (__half2*)sK;
    __half2* sP2  = (__half2*)sP;
    const uint32_t* q32 = (const uint32_t*)sQ;
    const uint32_t* k32 = (const uint32_t*)sK;
    const uint32_t* v32 = (const uint32_t*)sVt;
    const uint32_t* p32 = (const uint32_t*)sP;

    const int qt = blockIdx.x, h = blockIdx.y, b = blockIdx.z;
    const int kvh = h >> 2;
    const int tid = threadIdx.x, lane = tid & 31, w = tid >> 5;
    const int gid = lane >> 2, tig = lane & 3;
    const float scale = 0.08838834764831845f;   // 1/sqrt(128)

    // Q tile (128 x 128), scale folded, fp16
    for (int i = tid; i < 128 * 32; i += 256) {
        const int r = i >> 5, c4 = (i & 31) << 2;
        float4 qv = *(const float4*)&Q[(((size_t)(b * SEQ + qt * 128 + r)) * NH + h) * HD + c4];
        sQ2[r * FQW + (c4 >> 1)]     = __floats2half2_rn(qv.x * scale, qv.y * scale);
        sQ2[r * FQW + (c4 >> 1) + 1] = __floats2half2_rn(qv.z * scale, qv.w * scale);
    }

    float m0 = -1e30f, m1 = -1e30f, l0 = 0.f, l1 = 0.f;
    float o[16][4];
#pragma unroll
    for (int t = 0; t < 16; t++)
#pragma unroll
        for (int c = 0; c < 4; c++) o[t][c] = 0.f;

    const int r0 = 16 * w + gid;
    const int grow0 = qt * 128 + r0;
    const int grow1 = grow0 + 8;

    const int jmax = 2 * qt + 1;
    for (int j = 0; j <= jmax; j++) {
        __syncthreads();

        // K tile (64 x 128) fp16
        for (int i = tid; i < 64 * 32; i += 256) {
            const int r = i >> 5, c4 = (i & 31) << 2;
            float4 kv = *(const float4*)&K[(((size_t)(b * SEQ + j * 64 + r)) * NKV + kvh) * HD + c4];
            sK2[r * FQW + (c4 >> 1)]     = __floats2half2_rn(kv.x, kv.y);
            sK2[r * FQW + (c4 >> 1) + 1] = __floats2half2_rn(kv.z, kv.w);
        }
        // V tile transposed: sVt[d][kv]
        for (int i = tid; i < 64 * 32; i += 256) {
            const int r = i & 63, c4 = (i >> 6) << 2;
            float4 vv = *(const float4*)&V[(((size_t)(b * SEQ + j * 64 + r)) * NKV + kvh) * HD + c4];
            sVt[(c4 + 0) * 72 + r] = __float2half_rn(vv.x);
            sVt[(c4 + 1) * 72 + r] = __float2half_rn(vv.y);
            sVt[(c4 + 2) * 72 + r] = __float2half_rn(vv.z);
            sVt[(c4 + 3) * 72 + r] = __float2half_rn(vv.w);
        }
        __syncthreads();

        // S = Q K^T : 8 k-steps of 16, 8 n-tiles
        float sc[8][4];
#pragma unroll
        for (int t = 0; t < 8; t++)
#pragma unroll
            for (int c = 0; c < 4; c++) sc[t][c] = 0.f;

#pragma unroll
        for (int kk = 0; kk < 128; kk += 16) {
            const int kw = kk >> 1;
            uint32_t a[4];
            a[0] = q32[r0 * FQW + kw + tig];
            a[1] = q32[(r0 + 8) * FQW + kw + tig];
            a[2] = q32[r0 * FQW + kw + 4 + tig];
            a[3] = q32[(r0 + 8) * FQW + kw + 4 + tig];
#pragma unroll
            for (int t = 0; t < 8; t++) {
                uint32_t bf[2];
                bf[0] = k32[(8 * t + gid) * FQW + kw + tig];
                bf[1] = k32[(8 * t + gid) * FQW + kw + 4 + tig];
                mma_f16(sc[t], a, bf);
            }
        }

        // causal mask
        const int cb = j * 64 + 2 * tig;
#pragma unroll
        for (int t = 0; t < 8; t++) {
            const int c0 = cb + 8 * t, c1 = c0 + 1;
            if (c0 > grow0) sc[t][0] = -1e30f;
            if (c1 > grow0) sc[t][1] = -1e30f;
            if (c0 > grow1) sc[t][2] = -1e30f;
            if (c1 > grow1) sc[t][3] = -1e30f;
        }

        // online softmax
        float mx0 = -1e30f, mx1 = -1e30f;
#pragma unroll
        for (int t = 0; t < 8; t++) {
            mx0 = fmaxf(mx0, fmaxf(sc[t][0], sc[t][1]));
            mx1 = fmaxf(mx1, fmaxf(sc[t][2], sc[t][3]));
        }
        mx0 = fmaxf(mx0, __shfl_xor_sync(~0u, mx0, 1));
        mx0 = fmaxf(mx0, __shfl_xor_sync(~0u, mx0, 2));
        mx1 = fmaxf(mx1, __shfl_xor_sync(~0u, mx1, 1));
        mx1 = fmaxf(mx1, __shfl_xor_sync(~0u, mx1, 2));

        const float mn0 = fmaxf(m0, mx0), mn1 = fmaxf(m1, mx1);
        float rs0 = 0.f, rs1 = 0.f;
#pragma unroll
        for (int t = 0; t < 8; t++) {
            sc[t][0] = __expf(sc[t][0] - mn0);
            sc[t][1] = __expf(sc[t][1] - mn0);
            sc[t][2] = __expf(sc[t][2] - mn1);
            sc[t][3] = __expf(sc[t][3] - mn1);
            rs0 += sc[t][0] + sc[t][1];
            rs1 += sc[t][2] + sc[t][3];
        }
        rs0 += __shfl_xor_sync(~0u, rs0, 1); rs0 += __shfl_xor_sync(~0u, rs0, 2);
        rs1 += __shfl_xor_sync(~0u, rs1, 1); rs1 += __shfl_xor_sync(~0u, rs1, 2);

        const float al0 = __expf(m0 - mn0), al1 = __expf(m1 - mn1);
        l0 = l0 * al0 + rs0;  l1 = l1 * al1 + rs1;
        m0 = mn0;  m1 = mn1;

#pragma unroll
        for (int t = 0; t < 16; t++) {
            o[t][0] *= al0; o[t][1] *= al0;
            o[t][2] *= al1; o[t][3] *= al1;
        }

        // store P (fp16) to warp-private rows
#pragma unroll
        for (int t = 0; t < 8; t++) {
            sP2[r0 * FVW + 4 * t + tig]       = __floats2half2_rn(sc[t][0], sc[t][1]);
            sP2[(r0 + 8) * FVW + 4 * t + tig] = __floats2half2_rn(sc[t][2], sc[t][3]);
        }
        __syncwarp();

        // O += P @ V : 4 k-steps of 16, 16 n-tiles over d=128
#pragma unroll
        for (int kk = 0; kk < 64; kk += 16) {
            const int kw = kk >> 1;
            uint32_t a[4];
            a[0] = p32[r0 * FVW + kw + tig];
            a[1] = p32[(r0 + 8) * FVW + kw + tig];
            a[2] = p32[r0 * FVW + kw + 4 + tig];
            a[3] = p32[(r0 + 8) * FVW + kw + 4 + tig];
#pragma unroll
            for (int t = 0; t < 16; t++) {
                uint32_t bf[2];
                bf[0] = v32[(8 * t + gid) * FVW + kw + tig];
                bf[1] = v32[(8 * t + gid) * FVW + kw + 4 + tig];
                mma_f16(o[t], a, bf);
            }
        }
    }

    // epilogue: normalize, write fp16
    const float i0 = 1.f / l0, i1 = 1.f / l1;
#pragma unroll
    for (int t = 0; t < 16; t++) {
        const int col = 8 * t + 2 * tig;
        __half* d0 = &O[(((size_t)(b * SEQ + qt * 128 + r0)) * NH + h) * HD + col];
        __half* d1 = &O[(((size_t)(b * SEQ + qt * 128 + r0 + 8)) * NH + h) * HD + col];
        *(__half2*)d0 = __floats2half2_rn(o[t][0] * i0, o[t][1] * i0);
        *(__half2*)d1 = __floats2half2_rn(o[t][2] * i1, o[t][3] * i1);
    }
}

// ---------------------------------------------------------------------------
extern "C" void kernel_launch(void* const* d_in, const int* in_sizes, int n_in,
                              void* d_out, int out_size)
{
    const float* hs = (const float*)d_in[0];
    const int*   pos = (const int*)d_in[1];
    const float* wq = (const float*)d_in[2];
    const float* wk = (const float*)d_in[3];
    const float* wv = (const float*)d_in[4];
    const float* wo = (const float*)d_in[5];
    const float* qn = (const float*)d_in[6];
    const float* kn = (const float*)d_in[7];
    float* out = (float*)d_out;

    float *q, *k, *v;
    __half *attn, *hsh, *wqh, *wkh, *wvh, *woh;
    cudaGetSymbolAddress((void**)&q, g_q);
    cudaGetSymbolAddress((void**)&k, g_k);
    cudaGetSymbolAddress((void**)&v, g_v);
    cudaGetSymbolAddress((void**)&attn, g_attn);
    cudaGetSymbolAddress((void**)&hsh, g_hsh);
    cudaGetSymbolAddress((void**)&wqh, g_wqh);
    cudaGetSymbolAddress((void**)&wkh, g_wkh);
    cudaGetSymbolAddress((void**)&wvh, g_wvh);
    cudaGetSymbolAddress((void**)&woh, g_woh);

    const size_t gemm_smem = (size_t)3 * GSTAGEH * sizeof(__half);  // 110592 B
    cudaFuncSetAttribute(gemm_f16_kernel,
                         cudaFuncAttributeMaxDynamicSharedMemorySize, (int)gemm_smem);

    const size_t fa_smem = (size_t)(128 * 136 + 64 * 136 + 128 * 72 + 128 * 72) * sizeof(__half);
    cudaFuncSetAttribute(flash_f16_kernel,
                         cudaFuncAttributeMaxDynamicSharedMemorySize, (int)fa_smem);

    // f32 -> f16 conversions
    cvt_f16_kernel<<<(MTOT * HIDDEN) / 1024, 256>>>(hs, hsh);
    cvt_f16_kernel<<<(NH * HD * HIDDEN) / 1024, 256>>>(wq, wqh);
    cvt_f16_kernel<<<(NKV * HD * HIDDEN) / 1024, 256>>>(wk, wkh);
    cvt_f16_kernel<<<(NKV * HD * HIDDEN) / 1024, 256>>>(wv, wvh);
    cvt_f16_kernel<<<(HIDDEN * NH * HD) / 1024, 256>>>(wo, woh);

    // QKV projections (fp16 mma, f32 accum)
    gemm_f16_kernel<<<dim3(NH * HD / 128, MTOT / 128), 256, gemm_smem>>>(hsh, wqh, q, MTOT, NH * HD, HIDDEN);
    gemm_f16_kernel<<<dim3(NKV * HD / 128, MTOT / 128), 256, gemm_smem>>>(hsh, wkh, k, MTOT, NKV * HD, HIDDEN);
    gemm_f16_kernel<<<dim3(NKV * HD / 128, MTOT / 128), 256, gemm_smem>>>(hsh, wvh, v, MTOT, NKV * HD, HIDDEN);

    // Per-head LN + RoPE (fp32, in place)
    norm_rope_kernel<<<MTOT * NH, 128>>>(q, qn, pos, NH);
    norm_rope_kernel<<<MTOT * NKV, 128>>>(k, kn, pos, NKV);

    // Causal flash attention (fp16 mma) -> fp16 attn
    flash_f16_kernel<<<dim3(SEQ / 128, NH, BATCH), 256, fa_smem>>>(q, k, v, attn);

    // Output projection (fp16 mma, f32 accum)
    gemm_f16_kernel<<<dim3(HIDDEN / 128, MTOT / 128), 256, gemm_smem>>>(attn, woh, out, MTOT, HIDDEN, HIDDEN);
}